// round 2
// baseline (speedup 1.0000x reference)
#include <cuda_runtime.h>
#include <cuda_bf16.h>
#include <cstdint>

// Problem constants
#define BATCH   16
#define NQ      1024
#define NK      1024
#define DIN     512
#define NHEADS  8
#define HDIM    64
#define BN_TOT  (BATCH * NQ)       // 16384
#define NORM_F  0.125f             // 1/sqrt(64)

#define DEV_NEG_INF __int_as_float(0xff800000u)

// -------- scratch (device globals: allocation-free) --------
// Q/K/V: [h][b*1024+n][64]   (32 MB each)
// H    : [bn][h*64+v]        (32 MB)
__device__ float g_Q[(size_t)NHEADS * BN_TOT * HDIM];
__device__ float g_K[(size_t)NHEADS * BN_TOT * HDIM];
__device__ float g_V[(size_t)NHEADS * BN_TOT * HDIM];
__device__ float g_H[(size_t)BN_TOT * DIN];

// ============================================================
// Shared 128x64 fp32 GEMM tile: C[128,64] = X[128,512] @ W[512,64(+ld)]
// 256 threads, 8x4 microtile per thread, BK=16.
// ============================================================
__device__ __forceinline__ void gemm_tile_128x64(
    const float* __restrict__ X, int ldx,
    const float* __restrict__ W, int ldw,
    float*       __restrict__ C, int ldc,
    float (*Xs)[128], float (*Ws)[64])
{
    const int tid = threadIdx.x;
    const int tx  = tid & 15;   // N direction (16 x 4 cols)
    const int ty  = tid >> 4;   // M direction (16 x 8 rows)

    float acc[8][4];
#pragma unroll
    for (int i = 0; i < 8; i++)
#pragma unroll
        for (int j = 0; j < 4; j++) acc[i][j] = 0.f;

    for (int k0 = 0; k0 < DIN; k0 += 16) {
        // Load X tile (128x16) as float4, store transposed Xs[k][m]
#pragma unroll
        for (int l = tid; l < 512; l += 256) {
            int m  = l >> 2;
            int k4 = l & 3;
            float4 xv = *(const float4*)(X + (size_t)m * ldx + k0 + k4 * 4);
            Xs[k4 * 4 + 0][m] = xv.x;
            Xs[k4 * 4 + 1][m] = xv.y;
            Xs[k4 * 4 + 2][m] = xv.z;
            Xs[k4 * 4 + 3][m] = xv.w;
        }
        // Load W tile (16x64) as float4, row-major
        {
            int k = tid >> 4;
            int n = (tid & 15) * 4;
            *(float4*)(&Ws[k][n]) = *(const float4*)(W + (size_t)(k0 + k) * ldw + n);
        }
        __syncthreads();

#pragma unroll
        for (int k = 0; k < 16; k++) {
            float4 a0 = *(const float4*)(&Xs[k][ty * 8]);
            float4 a1 = *(const float4*)(&Xs[k][ty * 8 + 4]);
            float4 bb = *(const float4*)(&Ws[k][tx * 4]);
            float am[8] = {a0.x, a0.y, a0.z, a0.w, a1.x, a1.y, a1.z, a1.w};
            float bn[4] = {bb.x, bb.y, bb.z, bb.w};
#pragma unroll
            for (int i = 0; i < 8; i++)
#pragma unroll
                for (int j = 0; j < 4; j++)
                    acc[i][j] = fmaf(am[i], bn[j], acc[i][j]);
        }
        __syncthreads();
    }

#pragma unroll
    for (int i = 0; i < 8; i++) {
        float4 o = make_float4(acc[i][0], acc[i][1], acc[i][2], acc[i][3]);
        *(float4*)(C + (size_t)(ty * 8 + i) * ldc + tx * 4) = o;
    }
}

// ============================================================
// Kernel 1: fused QKV projections.
// grid = (128 m-tiles, 8 heads, 3 ops), 256 threads
// ============================================================
__global__ __launch_bounds__(256)
void qkv_proj(const float* __restrict__ q,
              const float* __restrict__ k,
              const float* __restrict__ v,
              const float* __restrict__ Wq,
              const float* __restrict__ Wk,
              const float* __restrict__ Wv)
{
    __shared__ float Xs[16][128];
    __shared__ float Ws[16][64];

    const int m0 = blockIdx.x * 128;
    const int h  = blockIdx.y;
    const int op = blockIdx.z;

    const float* X = (op == 0 ? q : (op == 1 ? k : v)) + (size_t)m0 * DIN;
    const float* W = (op == 0 ? Wq : (op == 1 ? Wk : Wv)) + (size_t)h * DIN * HDIM;
    float* C = (op == 0 ? g_Q : (op == 1 ? g_K : g_V))
               + (size_t)h * BN_TOT * HDIM + (size_t)m0 * HDIM;

    gemm_tile_128x64(X, DIN, W, HDIM, C, HDIM, Xs, Ws);
}

// ============================================================
// Kernel 2: flash attention (fp32 SIMT).
// grid = (8 q-tiles, 16 batch, 8 heads), 128 threads; thread t owns q-row q0+t.
// Mask arrives as int32 (bool inputs are materialized as int32 by the harness).
// ============================================================
#define KTILE 32

__global__ __launch_bounds__(128)
void attn_kernel(const int* __restrict__ mask)
{
    __shared__ __align__(16) float Ks[KTILE][HDIM];
    __shared__ __align__(16) float Vs[KTILE][HDIM];

    const int t  = threadIdx.x;
    const int q0 = blockIdx.x * 128;
    const int b  = blockIdx.y;
    const int h  = blockIdx.z;
    const int r  = q0 + t;

    // Load Q row into registers, pre-scaled by 1/sqrt(d)
    float qv[HDIM];
    {
        const float4* qp = (const float4*)(g_Q + ((size_t)(h * BATCH + b) * NQ + r) * HDIM);
#pragma unroll
        for (int d4 = 0; d4 < 16; d4++) {
            float4 t4 = qp[d4];
            qv[4 * d4 + 0] = t4.x * NORM_F;
            qv[4 * d4 + 1] = t4.y * NORM_F;
            qv[4 * d4 + 2] = t4.z * NORM_F;
            qv[4 * d4 + 3] = t4.w * NORM_F;
        }
    }

    float acc[HDIM];
#pragma unroll
    for (int i = 0; i < HDIM; i++) acc[i] = 0.f;
    float m_run = DEV_NEG_INF;
    float l_run = 0.f;

    const float4* Kg = (const float4*)(g_K + (size_t)(h * BATCH + b) * NK * HDIM);
    const float4* Vg = (const float4*)(g_V + (size_t)(h * BATCH + b) * NK * HDIM);
    const int* mrow = mask + ((size_t)b * NQ + r) * NK;
    float4* Ks4 = (float4*)Ks;
    float4* Vs4 = (float4*)Vs;

    for (int kt = 0; kt < NK / KTILE; kt++) {
        // Cooperative load of K/V tiles (contiguous 8KB each -> fully coalesced)
        const float4* Kt = Kg + (size_t)kt * KTILE * (HDIM / 4);
        const float4* Vt = Vg + (size_t)kt * KTILE * (HDIM / 4);
#pragma unroll
        for (int i = 0; i < (KTILE * HDIM / 4) / 128; i++) {
            Ks4[t + i * 128] = Kt[t + i * 128];
            Vs4[t + i * 128] = Vt[t + i * 128];
        }
        __syncthreads();

        // Mask words (int32 0/1) for this row/tile: 32 ints = 8 x int4
        union { int4 v4[8]; int w[32]; } mu;
        const int4* mp = (const int4*)(mrow + kt * KTILE);
#pragma unroll
        for (int i = 0; i < 8; i++) mu.v4[i] = mp[i];

        // Scores s[j] = qrow . K[j]
        float s[KTILE];
#pragma unroll
        for (int j = 0; j < KTILE; j++) {
            const float4* kr = (const float4*)Ks[j];
            float a0 = 0.f, a1 = 0.f, a2 = 0.f, a3 = 0.f;
#pragma unroll
            for (int d4 = 0; d4 < 16; d4++) {
                float4 kk = kr[d4];
                a0 = fmaf(qv[4 * d4 + 0], kk.x, a0);
                a1 = fmaf(qv[4 * d4 + 1], kk.y, a1);
                a2 = fmaf(qv[4 * d4 + 2], kk.z, a2);
                a3 = fmaf(qv[4 * d4 + 3], kk.w, a3);
            }
            s[j] = (a0 + a1) + (a2 + a3);
            if (mu.w[j] != 0) s[j] = DEV_NEG_INF;
        }

        // Online softmax update
        float tmax = DEV_NEG_INF;
#pragma unroll
        for (int j = 0; j < KTILE; j++) tmax = fmaxf(tmax, s[j]);
        float m_new = fmaxf(m_run, tmax);

        if (m_new > DEV_NEG_INF) {   // per-thread registers only: divergence-safe
            float scale = __expf(m_run - m_new);   // m_run=-inf -> 0
            float psum = 0.f;
#pragma unroll
            for (int j = 0; j < KTILE; j++) {
                s[j] = __expf(s[j] - m_new);       // masked (-inf) -> 0
                psum += s[j];
            }
            l_run = l_run * scale + psum;
#pragma unroll
            for (int i = 0; i < HDIM; i++) acc[i] *= scale;
#pragma unroll
            for (int j = 0; j < KTILE; j++) {
                float pj = s[j];
                const float4* vr = (const float4*)Vs[j];
#pragma unroll
                for (int d4 = 0; d4 < 16; d4++) {
                    float4 vvv = vr[d4];
                    acc[4 * d4 + 0] = fmaf(pj, vvv.x, acc[4 * d4 + 0]);
                    acc[4 * d4 + 1] = fmaf(pj, vvv.y, acc[4 * d4 + 1]);
                    acc[4 * d4 + 2] = fmaf(pj, vvv.z, acc[4 * d4 + 2]);
                    acc[4 * d4 + 3] = fmaf(pj, vvv.w, acc[4 * d4 + 3]);
                }
            }
            m_run = m_new;
        }
        __syncthreads();
    }

    // Normalize and write heads: g_H[bn][h*64+v]
    float inv = (l_run > 0.f) ? (1.f / l_run) : 0.f;
    float* orow = g_H + ((size_t)(b * NQ + r)) * DIN + h * HDIM;
#pragma unroll
    for (int d4 = 0; d4 < 16; d4++) {
        float4 o = make_float4(acc[4 * d4 + 0] * inv, acc[4 * d4 + 1] * inv,
                               acc[4 * d4 + 2] * inv, acc[4 * d4 + 3] * inv);
        *(float4*)(orow + 4 * d4) = o;
    }
}

// ============================================================
// Kernel 3: output projection: out[16384,512] = H[16384,512] @ Wo[512,512]
// grid = (128 m-tiles, 8 n-tiles), 256 threads
// ============================================================
__global__ __launch_bounds__(256)
void out_proj(const float* __restrict__ Wo, float* __restrict__ out)
{
    __shared__ float Xs[16][128];
    __shared__ float Ws[16][64];

    const int m0 = blockIdx.x * 128;
    const int n0 = blockIdx.y * 64;

    gemm_tile_128x64(g_H + (size_t)m0 * DIN, DIN,
                     Wo + n0, DIN,
                     out + (size_t)m0 * DIN + n0, DIN,
                     Xs, Ws);
}

// ============================================================
extern "C" void kernel_launch(void* const* d_in, const int* in_sizes, int n_in,
                              void* d_out, int out_size)
{
    const float* q  = (const float*)d_in[0];
    const float* k  = (const float*)d_in[1];
    const float* v  = (const float*)d_in[2];
    const int*   mask = (const int*)d_in[3];
    const float* Wq = (const float*)d_in[4];
    const float* Wk = (const float*)d_in[5];
    const float* Wv = (const float*)d_in[6];
    const float* Wo = (const float*)d_in[7];
    float* out = (float*)d_out;

    qkv_proj<<<dim3(BN_TOT / 128, NHEADS, 3), 256>>>(q, k, v, Wq, Wk, Wv);
    attn_kernel<<<dim3(NQ / 128, BATCH, NHEADS), 128>>>(mask);
    out_proj<<<dim3(BN_TOT / 128, DIN / 64), 256>>>(Wo, out);
}

// round 4
// speedup vs baseline: 1.1120x; 1.1120x over previous
#include <cuda_runtime.h>
#include <cuda_bf16.h>
#include <mma.h>
#include <cstdint>

using namespace nvcuda;

// Problem constants
#define BATCH   16
#define NQ      1024
#define NK      1024
#define DIN     512
#define NHEADS  8
#define HDIM    64
#define BN_TOT  (BATCH * NQ)       // 16384
#define NORM_F  0.125f             // 1/sqrt(64)

#define DEV_NEG_INF __int_as_float(0xff800000u)

// -------- scratch (device globals: allocation-free) --------
__device__ float g_Q[(size_t)NHEADS * BN_TOT * HDIM];   // [h][bn][64]
__device__ float g_K[(size_t)NHEADS * BN_TOT * HDIM];
__device__ float g_V[(size_t)NHEADS * BN_TOT * HDIM];
__device__ float g_H[(size_t)BN_TOT * DIN];             // [bn][h*64+v]

__device__ __forceinline__ float f2tf32_rna(float x) {
    uint32_t r;
    asm("cvt.rna.tf32.f32 %0, %1;" : "=r"(r) : "f"(x));
    return __uint_as_float(r);
}

// ============================================================
// wmma tf32 GEMM: per block, C[128,64] = A[128,512] @ B[512,64]
//   A: row-major, lda = 512 (fixed)
//   B: row-major [K, N-cols] with leading dim ldb (weights used in-place)
//   grid = (128 m-tiles, Ny), per-y offsets via bblk/cblk strides.
// 256 threads = 8 warps: 4 (M) x 2 (N), each warp 32x32 = 2x2 m16n16k8 frags.
// ============================================================
#define BK   32
#define LDA_S 40   // 32 + 8 pad (floats); row stride 160B (32B-aligned)
#define LDB_S 72   // 64 + 8 pad (floats); row stride 288B (32B-aligned)

__global__ __launch_bounds__(256)
void gemm_wmma(const float* __restrict__ A,
               const float* __restrict__ B,
               float* __restrict__ C,
               size_t bblk_stride, int ldb,
               size_t cblk_stride, int ldc)
{
    __shared__ __align__(32) float sA[128 * LDA_S];  // 20 KB
    __shared__ __align__(32) float sB[BK * LDB_S];   //  9 KB

    const int tid = threadIdx.x;
    const int wid = tid >> 5;
    const int wm  = wid & 3;    // 0..3  (M)
    const int wn  = wid >> 2;   // 0..1  (N)

    const float* At = A + (size_t)blockIdx.x * 128 * DIN;
    const float* Bt = B + (size_t)blockIdx.y * bblk_stride;
    float*       Ct = C + (size_t)blockIdx.y * cblk_stride
                        + (size_t)blockIdx.x * 128 * ldc;

    wmma::fragment<wmma::accumulator, 16, 16, 8, float> acc[2][2];
#pragma unroll
    for (int i = 0; i < 2; i++)
#pragma unroll
        for (int j = 0; j < 2; j++) wmma::fill_fragment(acc[i][j], 0.0f);

    for (int c = 0; c < DIN / BK; ++c) {
        const int k0 = c * BK;

        // Stage A chunk [128 x 32] (tf32-rounded): 1024 float4, 4/thread
#pragma unroll
        for (int i = 0; i < 4; ++i) {
            int idx = tid + i * 256;
            int m  = idx >> 3;
            int c4 = idx & 7;
            float4 xv = *(const float4*)(At + (size_t)m * DIN + k0 + c4 * 4);
            xv.x = f2tf32_rna(xv.x); xv.y = f2tf32_rna(xv.y);
            xv.z = f2tf32_rna(xv.z); xv.w = f2tf32_rna(xv.w);
            *(float4*)(sA + m * LDA_S + c4 * 4) = xv;
        }
        // Stage B chunk [32 x 64] (tf32-rounded): 512 float4, 2/thread
#pragma unroll
        for (int i = 0; i < 2; ++i) {
            int idx = tid + i * 256;
            int kk = idx >> 4;
            int c4 = idx & 15;
            float4 xv = *(const float4*)(Bt + (size_t)(k0 + kk) * ldb + c4 * 4);
            xv.x = f2tf32_rna(xv.x); xv.y = f2tf32_rna(xv.y);
            xv.z = f2tf32_rna(xv.z); xv.w = f2tf32_rna(xv.w);
            *(float4*)(sB + kk * LDB_S + c4 * 4) = xv;
        }
        __syncthreads();

#pragma unroll
        for (int ks = 0; ks < BK / 8; ++ks) {
            wmma::fragment<wmma::matrix_a, 16, 16, 8, wmma::precision::tf32, wmma::row_major> af[2];
            wmma::fragment<wmma::matrix_b, 16, 16, 8, wmma::precision::tf32, wmma::row_major> bf[2];
#pragma unroll
            for (int i = 0; i < 2; i++)
                wmma::load_matrix_sync(af[i], sA + (wm * 32 + i * 16) * LDA_S + ks * 8, LDA_S);
#pragma unroll
            for (int j = 0; j < 2; j++)
                wmma::load_matrix_sync(bf[j], sB + (ks * 8) * LDB_S + wn * 32 + j * 16, LDB_S);
#pragma unroll
            for (int i = 0; i < 2; i++)
#pragma unroll
                for (int j = 0; j < 2; j++)
                    wmma::mma_sync(acc[i][j], af[i], bf[j], acc[i][j]);
        }
        __syncthreads();
    }

#pragma unroll
    for (int i = 0; i < 2; i++)
#pragma unroll
        for (int j = 0; j < 2; j++)
            wmma::store_matrix_sync(
                Ct + (size_t)(wm * 32 + i * 16) * ldc + wn * 32 + j * 16,
                acc[i][j], ldc, wmma::mem_row_major);
}

// ============================================================
// Kernel 2: flash attention (fp32 SIMT) — unchanged from R2 pass.
// ============================================================
#define KTILE 32

__global__ __launch_bounds__(128)
void attn_kernel(const int* __restrict__ mask)
{
    __shared__ __align__(16) float Ks[KTILE][HDIM];
    __shared__ __align__(16) float Vs[KTILE][HDIM];

    const int t  = threadIdx.x;
    const int q0 = blockIdx.x * 128;
    const int b  = blockIdx.y;
    const int h  = blockIdx.z;
    const int r  = q0 + t;

    float qv[HDIM];
    {
        const float4* qp = (const float4*)(g_Q + ((size_t)(h * BATCH + b) * NQ + r) * HDIM);
#pragma unroll
        for (int d4 = 0; d4 < 16; d4++) {
            float4 t4 = qp[d4];
            qv[4 * d4 + 0] = t4.x * NORM_F;
            qv[4 * d4 + 1] = t4.y * NORM_F;
            qv[4 * d4 + 2] = t4.z * NORM_F;
            qv[4 * d4 + 3] = t4.w * NORM_F;
        }
    }

    float acc[HDIM];
#pragma unroll
    for (int i = 0; i < HDIM; i++) acc[i] = 0.f;
    float m_run = DEV_NEG_INF;
    float l_run = 0.f;

    const float4* Kg = (const float4*)(g_K + (size_t)(h * BATCH + b) * NK * HDIM);
    const float4* Vg = (const float4*)(g_V + (size_t)(h * BATCH + b) * NK * HDIM);
    const int* mrow = mask + ((size_t)b * NQ + r) * NK;
    float4* Ks4 = (float4*)Ks;
    float4* Vs4 = (float4*)Vs;

    for (int kt = 0; kt < NK / KTILE; kt++) {
        const float4* Kt = Kg + (size_t)kt * KTILE * (HDIM / 4);
        const float4* Vt = Vg + (size_t)kt * KTILE * (HDIM / 4);
#pragma unroll
        for (int i = 0; i < (KTILE * HDIM / 4) / 128; i++) {
            Ks4[t + i * 128] = Kt[t + i * 128];
            Vs4[t + i * 128] = Vt[t + i * 128];
        }
        __syncthreads();

        union { int4 v4[8]; int w[32]; } mu;
        const int4* mp = (const int4*)(mrow + kt * KTILE);
#pragma unroll
        for (int i = 0; i < 8; i++) mu.v4[i] = mp[i];

        float s[KTILE];
#pragma unroll
        for (int j = 0; j < KTILE; j++) {
            const float4* kr = (const float4*)Ks[j];
            float a0 = 0.f, a1 = 0.f, a2 = 0.f, a3 = 0.f;
#pragma unroll
            for (int d4 = 0; d4 < 16; d4++) {
                float4 kk = kr[d4];
                a0 = fmaf(qv[4 * d4 + 0], kk.x, a0);
                a1 = fmaf(qv[4 * d4 + 1], kk.y, a1);
                a2 = fmaf(qv[4 * d4 + 2], kk.z, a2);
                a3 = fmaf(qv[4 * d4 + 3], kk.w, a3);
            }
            s[j] = (a0 + a1) + (a2 + a3);
            if (mu.w[j] != 0) s[j] = DEV_NEG_INF;
        }

        float tmax = DEV_NEG_INF;
#pragma unroll
        for (int j = 0; j < KTILE; j++) tmax = fmaxf(tmax, s[j]);
        float m_new = fmaxf(m_run, tmax);

        if (m_new > DEV_NEG_INF) {
            float scale = __expf(m_run - m_new);
            float psum = 0.f;
#pragma unroll
            for (int j = 0; j < KTILE; j++) {
                s[j] = __expf(s[j] - m_new);
                psum += s[j];
            }
            l_run = l_run * scale + psum;
#pragma unroll
            for (int i = 0; i < HDIM; i++) acc[i] *= scale;
#pragma unroll
            for (int j = 0; j < KTILE; j++) {
                float pj = s[j];
                const float4* vr = (const float4*)Vs[j];
#pragma unroll
                for (int d4 = 0; d4 < 16; d4++) {
                    float4 vvv = vr[d4];
                    acc[4 * d4 + 0] = fmaf(pj, vvv.x, acc[4 * d4 + 0]);
                    acc[4 * d4 + 1] = fmaf(pj, vvv.y, acc[4 * d4 + 1]);
                    acc[4 * d4 + 2] = fmaf(pj, vvv.z, acc[4 * d4 + 2]);
                    acc[4 * d4 + 3] = fmaf(pj, vvv.w, acc[4 * d4 + 3]);
                }
            }
            m_run = m_new;
        }
        __syncthreads();
    }

    float inv = (l_run > 0.f) ? (1.f / l_run) : 0.f;
    float* orow = g_H + ((size_t)(b * NQ + r)) * DIN + h * HDIM;
#pragma unroll
    for (int d4 = 0; d4 < 16; d4++) {
        float4 o = make_float4(acc[4 * d4 + 0] * inv, acc[4 * d4 + 1] * inv,
                               acc[4 * d4 + 2] * inv, acc[4 * d4 + 3] * inv);
        *(float4*)(orow + 4 * d4) = o;
    }
}

// ============================================================
extern "C" void kernel_launch(void* const* d_in, const int* in_sizes, int n_in,
                              void* d_out, int out_size)
{
    const float* q  = (const float*)d_in[0];
    const float* k  = (const float*)d_in[1];
    const float* v  = (const float*)d_in[2];
    const int*   mask = (const int*)d_in[3];
    const float* Wq = (const float*)d_in[4];
    const float* Wk = (const float*)d_in[5];
    const float* Wv = (const float*)d_in[6];
    const float* Wo = (const float*)d_in[7];
    float* out = (float*)d_out;

    float *pQ, *pK, *pV, *pH;
    cudaGetSymbolAddress((void**)&pQ, g_Q);
    cudaGetSymbolAddress((void**)&pK, g_K);
    cudaGetSymbolAddress((void**)&pV, g_V);
    cudaGetSymbolAddress((void**)&pH, g_H);

    // QKV projections: W_x[h] is [512,64] row-major -> used in place.
    // Per-head strides: B += h*512*64, C += h*BN_TOT*64.
    gemm_wmma<<<dim3(BN_TOT / 128, NHEADS), 256>>>(
        q, Wq, pQ, (size_t)DIN * HDIM, HDIM, (size_t)BN_TOT * HDIM, HDIM);
    gemm_wmma<<<dim3(BN_TOT / 128, NHEADS), 256>>>(
        k, Wk, pK, (size_t)DIN * HDIM, HDIM, (size_t)BN_TOT * HDIM, HDIM);
    gemm_wmma<<<dim3(BN_TOT / 128, NHEADS), 256>>>(
        v, Wv, pV, (size_t)DIN * HDIM, HDIM, (size_t)BN_TOT * HDIM, HDIM);

    attn_kernel<<<dim3(NQ / 128, BATCH, NHEADS), 128>>>(mask);

    // Output projection: Wo as [512(k), 512(e)] row-major; 8 column tiles of 64.
    gemm_wmma<<<dim3(BN_TOT / 128, DIN / HDIM), 256>>>(
        pH, Wo, out, (size_t)HDIM, DIN, (size_t)HDIM, DIN);
}

// round 5
// speedup vs baseline: 1.3489x; 1.2131x over previous
#include <cuda_runtime.h>
#include <cuda_bf16.h>
#include <mma.h>
#include <cstdint>

using namespace nvcuda;

// Problem constants
#define BATCH   16
#define NQ      1024
#define NK      1024
#define DIN     512
#define NHEADS  8
#define HDIM    64
#define BN_TOT  (BATCH * NQ)       // 16384
#define NORM_F  0.125f             // 1/sqrt(64)

// -------- scratch (device globals: allocation-free) --------
__device__ float g_Q[(size_t)NHEADS * BN_TOT * HDIM];   // [h][bn][64]
__device__ float g_K[(size_t)NHEADS * BN_TOT * HDIM];
__device__ float g_V[(size_t)NHEADS * BN_TOT * HDIM];
__device__ float g_H[(size_t)BN_TOT * DIN];             // [bn][h*64+v]

__device__ __forceinline__ float f2tf32_rna(float x) {
    uint32_t r;
    asm("cvt.rna.tf32.f32 %0, %1;" : "=r"(r) : "f"(x));
    return __uint_as_float(r);
}

// ============================================================
// SIMT fp32 GEMM tile (exact; for QKV projections). From R2 (measured good).
// C[128,64] = X[128,512] @ W[512,64]; 256 thr, 8x4 microtile, BK=16.
// ============================================================
__device__ __forceinline__ void gemm_tile_128x64(
    const float* __restrict__ X, int ldx,
    const float* __restrict__ W, int ldw,
    float*       __restrict__ C, int ldc,
    float (*Xs)[128], float (*Ws)[64])
{
    const int tid = threadIdx.x;
    const int tx  = tid & 15;
    const int ty  = tid >> 4;

    float acc[8][4];
#pragma unroll
    for (int i = 0; i < 8; i++)
#pragma unroll
        for (int j = 0; j < 4; j++) acc[i][j] = 0.f;

    for (int k0 = 0; k0 < DIN; k0 += 16) {
#pragma unroll
        for (int l = tid; l < 512; l += 256) {
            int m  = l >> 2;
            int k4 = l & 3;
            float4 xv = *(const float4*)(X + (size_t)m * ldx + k0 + k4 * 4);
            Xs[k4 * 4 + 0][m] = xv.x;
            Xs[k4 * 4 + 1][m] = xv.y;
            Xs[k4 * 4 + 2][m] = xv.z;
            Xs[k4 * 4 + 3][m] = xv.w;
        }
        {
            int k = tid >> 4;
            int n = (tid & 15) * 4;
            *(float4*)(&Ws[k][n]) = *(const float4*)(W + (size_t)(k0 + k) * ldw + n);
        }
        __syncthreads();

#pragma unroll
        for (int k = 0; k < 16; k++) {
            float4 a0 = *(const float4*)(&Xs[k][ty * 8]);
            float4 a1 = *(const float4*)(&Xs[k][ty * 8 + 4]);
            float4 bb = *(const float4*)(&Ws[k][tx * 4]);
            float am[8] = {a0.x, a0.y, a0.z, a0.w, a1.x, a1.y, a1.z, a1.w};
            float bn[4] = {bb.x, bb.y, bb.z, bb.w};
#pragma unroll
            for (int i = 0; i < 8; i++)
#pragma unroll
                for (int j = 0; j < 4; j++)
                    acc[i][j] = fmaf(am[i], bn[j], acc[i][j]);
        }
        __syncthreads();
    }

#pragma unroll
    for (int i = 0; i < 8; i++) {
        float4 o = make_float4(acc[i][0], acc[i][1], acc[i][2], acc[i][3]);
        *(float4*)(C + (size_t)(ty * 8 + i) * ldc + tx * 4) = o;
    }
}

__global__ __launch_bounds__(256)
void qkv_proj(const float* __restrict__ q,
              const float* __restrict__ k,
              const float* __restrict__ v,
              const float* __restrict__ Wq,
              const float* __restrict__ Wk,
              const float* __restrict__ Wv)
{
    __shared__ float Xs[16][128];
    __shared__ float Ws[16][64];

    const int m0 = blockIdx.x * 128;
    const int h  = blockIdx.y;
    const int op = blockIdx.z;

    const float* X = (op == 0 ? q : (op == 1 ? k : v)) + (size_t)m0 * DIN;
    const float* W = (op == 0 ? Wq : (op == 1 ? Wk : Wv)) + (size_t)h * DIN * HDIM;
    float* C = (op == 0 ? g_Q : (op == 1 ? g_K : g_V))
               + (size_t)h * BN_TOT * HDIM + (size_t)m0 * HDIM;

    gemm_tile_128x64(X, DIN, W, HDIM, C, HDIM, Xs, Ws);
}

// ============================================================
// wmma tf32 GEMM (for out projection). From R4 (measured good).
// ============================================================
#define BK    32
#define LDA_S 40
#define LDB_S 72

__global__ __launch_bounds__(256)
void gemm_wmma(const float* __restrict__ A,
               const float* __restrict__ B,
               float* __restrict__ C,
               size_t bblk_stride, int ldb,
               size_t cblk_stride, int ldc)
{
    __shared__ __align__(32) float sA[128 * LDA_S];
    __shared__ __align__(32) float sB[BK * LDB_S];

    const int tid = threadIdx.x;
    const int wid = tid >> 5;
    const int wm  = wid & 3;
    const int wn  = wid >> 2;

    const float* At = A + (size_t)blockIdx.x * 128 * DIN;
    const float* Bt = B + (size_t)blockIdx.y * bblk_stride;
    float*       Ct = C + (size_t)blockIdx.y * cblk_stride
                        + (size_t)blockIdx.x * 128 * ldc;

    wmma::fragment<wmma::accumulator, 16, 16, 8, float> acc[2][2];
#pragma unroll
    for (int i = 0; i < 2; i++)
#pragma unroll
        for (int j = 0; j < 2; j++) wmma::fill_fragment(acc[i][j], 0.0f);

    for (int c = 0; c < DIN / BK; ++c) {
        const int k0 = c * BK;
#pragma unroll
        for (int i = 0; i < 4; ++i) {
            int idx = tid + i * 256;
            int m  = idx >> 3;
            int c4 = idx & 7;
            float4 xv = *(const float4*)(At + (size_t)m * DIN + k0 + c4 * 4);
            xv.x = f2tf32_rna(xv.x); xv.y = f2tf32_rna(xv.y);
            xv.z = f2tf32_rna(xv.z); xv.w = f2tf32_rna(xv.w);
            *(float4*)(sA + m * LDA_S + c4 * 4) = xv;
        }
#pragma unroll
        for (int i = 0; i < 2; ++i) {
            int idx = tid + i * 256;
            int kk = idx >> 4;
            int c4 = idx & 15;
            float4 xv = *(const float4*)(Bt + (size_t)(k0 + kk) * ldb + c4 * 4);
            xv.x = f2tf32_rna(xv.x); xv.y = f2tf32_rna(xv.y);
            xv.z = f2tf32_rna(xv.z); xv.w = f2tf32_rna(xv.w);
            *(float4*)(sB + kk * LDB_S + c4 * 4) = xv;
        }
        __syncthreads();

#pragma unroll
        for (int ks = 0; ks < BK / 8; ++ks) {
            wmma::fragment<wmma::matrix_a, 16, 16, 8, wmma::precision::tf32, wmma::row_major> af[2];
            wmma::fragment<wmma::matrix_b, 16, 16, 8, wmma::precision::tf32, wmma::row_major> bf[2];
#pragma unroll
            for (int i = 0; i < 2; i++)
                wmma::load_matrix_sync(af[i], sA + (wm * 32 + i * 16) * LDA_S + ks * 8, LDA_S);
#pragma unroll
            for (int j = 0; j < 2; j++)
                wmma::load_matrix_sync(bf[j], sB + (ks * 8) * LDB_S + wn * 32 + j * 16, LDB_S);
#pragma unroll
            for (int i = 0; i < 2; i++)
#pragma unroll
                for (int j = 0; j < 2; j++)
                    wmma::mma_sync(acc[i][j], af[i], bf[j], acc[i][j]);
        }
        __syncthreads();
    }

#pragma unroll
    for (int i = 0; i < 2; i++)
#pragma unroll
        for (int j = 0; j < 2; j++)
            wmma::store_matrix_sync(
                Ct + (size_t)(wm * 32 + i * 16) * ldc + wn * 32 + j * 16,
                acc[i][j], ldc, wmma::mem_row_major);
}

// ============================================================
// wmma tf32 flash attention.
// Block: 256 threads (8 warps = 4M x 2N), 128 q-rows of one (b,h).
// Loops 16 key-tiles of 64. grid = (8, 16, 8).
// smem (dynamic): sQ[128][68], sK[64][68], sV[64][68], sS[128][68]  = 102 KB
// Thread t owns q-row t/2, half-row (t&1)*32 for softmax + O accum.
// Mask folded as s += mask * -1e30 (branch-free; max stays finite).
// ============================================================
#define QT    128
#define KT    64
#define LDS_A 68
#define ATTN_SMEM ((QT * LDS_A + KT * LDS_A + KT * LDS_A + QT * LDS_A) * 4)

__global__ __launch_bounds__(256)
void attn_wmma(const int* __restrict__ mask)
{
    extern __shared__ float sm[];
    float* sQ = sm;
    float* sK = sQ + QT * LDS_A;
    float* sV = sK + KT * LDS_A;
    float* sS = sV + KT * LDS_A;

    const int tid = threadIdx.x;
    const int wid = tid >> 5;
    const int wm  = wid & 3;    // M: 4 warps of 32 rows
    const int wn  = wid >> 2;   // N: 2 warps of 32 cols
    const int q0  = blockIdx.x * QT;
    const int b   = blockIdx.y;
    const int h   = blockIdx.z;

    const int rt = tid >> 1;          // owned q-row (0..127)
    const int ch = (tid & 1) * 32;    // owned half-row offset

    const float* Qg = g_Q + ((size_t)(h * BATCH + b) * NQ + q0) * HDIM;
    const float* Kg = g_K + (size_t)(h * BATCH + b) * NK * HDIM;
    const float* Vg = g_V + (size_t)(h * BATCH + b) * NK * HDIM;

    // Stage Q (scaled by 1/sqrt(d), tf32-rounded): 2048 float4, 8/thread
#pragma unroll
    for (int i = 0; i < 8; ++i) {
        int idx = tid + i * 256;
        int m  = idx >> 4;
        int c4 = idx & 15;
        float4 xv = *(const float4*)(Qg + (size_t)m * HDIM + c4 * 4);
        xv.x = f2tf32_rna(xv.x * NORM_F); xv.y = f2tf32_rna(xv.y * NORM_F);
        xv.z = f2tf32_rna(xv.z * NORM_F); xv.w = f2tf32_rna(xv.w * NORM_F);
        *(float4*)(sQ + m * LDS_A + c4 * 4) = xv;
    }

    float O[32];
#pragma unroll
    for (int i = 0; i < 32; ++i) O[i] = 0.f;
    float m_run = -1e30f;
    float l_run = 0.f;

    const int* mrow = mask + ((size_t)b * NQ + q0 + rt) * NK + ch;
    float* srow = sS + rt * LDS_A + ch;

    for (int kt = 0; kt < NK / KT; ++kt) {
        // Stage K and V tiles [64 x 64] (tf32-rounded): 1024 float4 each
#pragma unroll
        for (int i = 0; i < 4; ++i) {
            int idx = tid + i * 256;
            int r  = idx >> 4;
            int c4 = idx & 15;
            float4 kv = *(const float4*)(Kg + (size_t)(kt * KT + r) * HDIM + c4 * 4);
            kv.x = f2tf32_rna(kv.x); kv.y = f2tf32_rna(kv.y);
            kv.z = f2tf32_rna(kv.z); kv.w = f2tf32_rna(kv.w);
            *(float4*)(sK + r * LDS_A + c4 * 4) = kv;
            float4 vv = *(const float4*)(Vg + (size_t)(kt * KT + r) * HDIM + c4 * 4);
            vv.x = f2tf32_rna(vv.x); vv.y = f2tf32_rna(vv.y);
            vv.z = f2tf32_rna(vv.z); vv.w = f2tf32_rna(vv.w);
            *(float4*)(sV + r * LDS_A + c4 * 4) = vv;
        }
        __syncthreads();

        // ---- S = Q @ K^T (tf32 MMA). col_major B gives the transpose. ----
        {
            wmma::fragment<wmma::accumulator, 16, 16, 8, float> sc[2][2];
#pragma unroll
            for (int i = 0; i < 2; i++)
#pragma unroll
                for (int j = 0; j < 2; j++) wmma::fill_fragment(sc[i][j], 0.0f);

#pragma unroll
            for (int ks = 0; ks < HDIM / 8; ++ks) {
                wmma::fragment<wmma::matrix_a, 16, 16, 8, wmma::precision::tf32, wmma::row_major> af[2];
                wmma::fragment<wmma::matrix_b, 16, 16, 8, wmma::precision::tf32, wmma::col_major> bf[2];
#pragma unroll
                for (int i = 0; i < 2; i++)
                    wmma::load_matrix_sync(af[i], sQ + (wm * 32 + i * 16) * LDS_A + ks * 8, LDS_A);
#pragma unroll
                for (int j = 0; j < 2; j++)
                    wmma::load_matrix_sync(bf[j], sK + (wn * 32 + j * 16) * LDS_A + ks * 8, LDS_A);
#pragma unroll
                for (int i = 0; i < 2; i++)
#pragma unroll
                    for (int j = 0; j < 2; j++)
                        wmma::mma_sync(sc[i][j], af[i], bf[j], sc[i][j]);
            }
#pragma unroll
            for (int i = 0; i < 2; i++)
#pragma unroll
                for (int j = 0; j < 2; j++)
                    wmma::store_matrix_sync(
                        sS + (wm * 32 + i * 16) * LDS_A + wn * 32 + j * 16,
                        sc[i][j], LDS_A, wmma::mem_row_major);
        }
        __syncthreads();

        // ---- online softmax on owned half-row ----
        {
            union { int4 v4[8]; int w[32]; } mu;
            const int4* mp = (const int4*)(mrow + kt * KT);
#pragma unroll
            for (int i = 0; i < 8; i++) mu.v4[i] = mp[i];

            float sv[32];
            float tmax = -1e30f;
#pragma unroll
            for (int j = 0; j < 8; ++j) {
                float4 s4 = *(const float4*)(srow + j * 4);
                sv[4*j+0] = fmaf((float)mu.w[4*j+0], -1e30f, s4.x);
                sv[4*j+1] = fmaf((float)mu.w[4*j+1], -1e30f, s4.y);
                sv[4*j+2] = fmaf((float)mu.w[4*j+2], -1e30f, s4.z);
                sv[4*j+3] = fmaf((float)mu.w[4*j+3], -1e30f, s4.w);
            }
#pragma unroll
            for (int j = 0; j < 32; ++j) tmax = fmaxf(tmax, sv[j]);
            tmax = fmaxf(tmax, __shfl_xor_sync(0xffffffffu, tmax, 1));
            float m_new = fmaxf(m_run, tmax);

            float scale = __expf(m_run - m_new);   // first tile: exp(0)=1, O=0
            float psum = 0.f;
#pragma unroll
            for (int j = 0; j < 8; ++j) {
                float p0 = __expf(sv[4*j+0] - m_new);
                float p1 = __expf(sv[4*j+1] - m_new);
                float p2 = __expf(sv[4*j+2] - m_new);
                float p3 = __expf(sv[4*j+3] - m_new);
                psum += (p0 + p1) + (p2 + p3);
                float4 p4 = make_float4(f2tf32_rna(p0), f2tf32_rna(p1),
                                        f2tf32_rna(p2), f2tf32_rna(p3));
                *(float4*)(srow + j * 4) = p4;
            }
            psum += __shfl_xor_sync(0xffffffffu, psum, 1);
            l_run = l_run * scale + psum;
#pragma unroll
            for (int i = 0; i < 32; ++i) O[i] *= scale;
            m_run = m_new;
        }
        __syncthreads();   // P fully written before MMA reads

        // ---- PV = P @ V (tf32 MMA), result back into sS ----
        {
            wmma::fragment<wmma::accumulator, 16, 16, 8, float> pc[2][2];
#pragma unroll
            for (int i = 0; i < 2; i++)
#pragma unroll
                for (int j = 0; j < 2; j++) wmma::fill_fragment(pc[i][j], 0.0f);

#pragma unroll
            for (int ks = 0; ks < KT / 8; ++ks) {
                wmma::fragment<wmma::matrix_a, 16, 16, 8, wmma::precision::tf32, wmma::row_major> af[2];
                wmma::fragment<wmma::matrix_b, 16, 16, 8, wmma::precision::tf32, wmma::row_major> bf[2];
#pragma unroll
                for (int i = 0; i < 2; i++)
                    wmma::load_matrix_sync(af[i], sS + (wm * 32 + i * 16) * LDS_A + ks * 8, LDS_A);
#pragma unroll
                for (int j = 0; j < 2; j++)
                    wmma::load_matrix_sync(bf[j], sV + (ks * 8) * LDS_A + wn * 32 + j * 16, LDS_A);
#pragma unroll
                for (int i = 0; i < 2; i++)
#pragma unroll
                    for (int j = 0; j < 2; j++)
                        wmma::mma_sync(pc[i][j], af[i], bf[j], pc[i][j]);
            }
            __syncthreads();   // all warps done reading P before overwrite
#pragma unroll
            for (int i = 0; i < 2; i++)
#pragma unroll
                for (int j = 0; j < 2; j++)
                    wmma::store_matrix_sync(
                        sS + (wm * 32 + i * 16) * LDS_A + wn * 32 + j * 16,
                        pc[i][j], LDS_A, wmma::mem_row_major);
        }
        __syncthreads();

        // ---- accumulate owned half-row of PV into O ----
#pragma unroll
        for (int j = 0; j < 8; ++j) {
            float4 p4 = *(const float4*)(srow + j * 4);
            O[4*j+0] += p4.x; O[4*j+1] += p4.y;
            O[4*j+2] += p4.z; O[4*j+3] += p4.w;
        }
        // next iteration's staging sync orders these reads vs. sS overwrite
    }

    // Normalize and write to g_H[bn][h*64 + v]
    float inv = (l_run > 0.f) ? (1.f / l_run) : 0.f;
    float* orow = g_H + ((size_t)(b * NQ + q0 + rt)) * DIN + h * HDIM + ch;
#pragma unroll
    for (int j = 0; j < 8; ++j) {
        float4 o = make_float4(O[4*j+0] * inv, O[4*j+1] * inv,
                               O[4*j+2] * inv, O[4*j+3] * inv);
        *(float4*)(orow + j * 4) = o;
    }
}

// ============================================================
extern "C" void kernel_launch(void* const* d_in, const int* in_sizes, int n_in,
                              void* d_out, int out_size)
{
    const float* q  = (const float*)d_in[0];
    const float* k  = (const float*)d_in[1];
    const float* v  = (const float*)d_in[2];
    const int*   mask = (const int*)d_in[3];
    const float* Wq = (const float*)d_in[4];
    const float* Wk = (const float*)d_in[5];
    const float* Wv = (const float*)d_in[6];
    const float* Wo = (const float*)d_in[7];
    float* out = (float*)d_out;

    float *pH;
    cudaGetSymbolAddress((void**)&pH, g_H);

    static bool attr_set = false;
    if (!attr_set) {
        cudaFuncSetAttribute(attn_wmma,
                             cudaFuncAttributeMaxDynamicSharedMemorySize,
                             ATTN_SMEM);
        attr_set = true;
    }

    // QKV projections: exact fp32 SIMT (protects the softmax error budget)
    qkv_proj<<<dim3(BN_TOT / 128, NHEADS, 3), 256>>>(q, k, v, Wq, Wk, Wv);

    // Flash attention (wmma tf32)
    attn_wmma<<<dim3(NQ / QT, BATCH, NHEADS), 256, ATTN_SMEM>>>(mask);

    // Output projection: wmma tf32; Wo is [512(k), 512(e)] row-major
    gemm_wmma<<<dim3(BN_TOT / 128, DIN / HDIM), 256>>>(
        pH, Wo, out, (size_t)HDIM, DIN, (size_t)HDIM, DIN);
}

// round 6
// speedup vs baseline: 1.9236x; 1.4260x over previous
#include <cuda_runtime.h>
#include <cuda_bf16.h>
#include <mma.h>
#include <cstdint>

using namespace nvcuda;

// Problem constants
#define BATCH   16
#define NQ      1024
#define NK      1024
#define DIN     512
#define NHEADS  8
#define HDIM    64
#define BN_TOT  (BATCH * NQ)       // 16384
#define NORM_F  0.125f             // 1/sqrt(64)

// -------- scratch (device globals: allocation-free) --------
__device__ float g_Q[(size_t)NHEADS * BN_TOT * HDIM];   // [h][bn][64]
__device__ float g_K[(size_t)NHEADS * BN_TOT * HDIM];
__device__ float g_V[(size_t)NHEADS * BN_TOT * HDIM];
__device__ float g_H[(size_t)BN_TOT * DIN];             // [bn][h*64+v]
__device__ unsigned long long g_Mb[(size_t)BN_TOT * (NK / 64)];  // packed mask bits

__device__ __forceinline__ float f2tf32_rna(float x) {
    uint32_t r;
    asm("cvt.rna.tf32.f32 %0, %1;" : "=r"(r) : "f"(x));
    return __uint_as_float(r);
}

// m16n8k8 tf32 mma with documented register layout (g=lane>>2, t=lane&3):
//   A: a0(g,t) a1(g+8,t) a2(g,t+4) a3(g+8,t+4)
//   B: b0(k=t,n=g) b1(k=t+4,n=g)
//   C: c0(g,2t) c1(g,2t+1) c2(g+8,2t) c3(g+8,2t+1)
__device__ __forceinline__ void mma_tf32(float* c, const uint32_t* a, const uint32_t* b) {
    asm volatile(
        "mma.sync.aligned.m16n8k8.row.col.f32.tf32.tf32.f32 "
        "{%0,%1,%2,%3}, {%4,%5,%6,%7}, {%8,%9}, {%0,%1,%2,%3};"
        : "+f"(c[0]), "+f"(c[1]), "+f"(c[2]), "+f"(c[3])
        : "r"(a[0]), "r"(a[1]), "r"(a[2]), "r"(a[3]), "r"(b[0]), "r"(b[1]));
}

// ============================================================
// SIMT fp32 GEMM tile (exact; QKV projections). Measured good (R2/R5).
// ============================================================
__device__ __forceinline__ void gemm_tile_128x64(
    const float* __restrict__ X, int ldx,
    const float* __restrict__ W, int ldw,
    float*       __restrict__ C, int ldc,
    float (*Xs)[128], float (*Ws)[64])
{
    const int tid = threadIdx.x;
    const int tx  = tid & 15;
    const int ty  = tid >> 4;

    float acc[8][4];
#pragma unroll
    for (int i = 0; i < 8; i++)
#pragma unroll
        for (int j = 0; j < 4; j++) acc[i][j] = 0.f;

    for (int k0 = 0; k0 < DIN; k0 += 16) {
#pragma unroll
        for (int l = tid; l < 512; l += 256) {
            int m  = l >> 2;
            int k4 = l & 3;
            float4 xv = *(const float4*)(X + (size_t)m * ldx + k0 + k4 * 4);
            Xs[k4 * 4 + 0][m] = xv.x;
            Xs[k4 * 4 + 1][m] = xv.y;
            Xs[k4 * 4 + 2][m] = xv.z;
            Xs[k4 * 4 + 3][m] = xv.w;
        }
        {
            int k = tid >> 4;
            int n = (tid & 15) * 4;
            *(float4*)(&Ws[k][n]) = *(const float4*)(W + (size_t)(k0 + k) * ldw + n);
        }
        __syncthreads();

#pragma unroll
        for (int k = 0; k < 16; k++) {
            float4 a0 = *(const float4*)(&Xs[k][ty * 8]);
            float4 a1 = *(const float4*)(&Xs[k][ty * 8 + 4]);
            float4 bb = *(const float4*)(&Ws[k][tx * 4]);
            float am[8] = {a0.x, a0.y, a0.z, a0.w, a1.x, a1.y, a1.z, a1.w};
            float bn[4] = {bb.x, bb.y, bb.z, bb.w};
#pragma unroll
            for (int i = 0; i < 8; i++)
#pragma unroll
                for (int j = 0; j < 4; j++)
                    acc[i][j] = fmaf(am[i], bn[j], acc[i][j]);
        }
        __syncthreads();
    }

#pragma unroll
    for (int i = 0; i < 8; i++) {
        float4 o = make_float4(acc[i][0], acc[i][1], acc[i][2], acc[i][3]);
        *(float4*)(C + (size_t)(ty * 8 + i) * ldc + tx * 4) = o;
    }
}

__global__ __launch_bounds__(256)
void qkv_proj(const float* __restrict__ q,
              const float* __restrict__ k,
              const float* __restrict__ v,
              const float* __restrict__ Wq,
              const float* __restrict__ Wk,
              const float* __restrict__ Wv)
{
    __shared__ float Xs[16][128];
    __shared__ float Ws[16][64];

    const int m0 = blockIdx.x * 128;
    const int h  = blockIdx.y;
    const int op = blockIdx.z;

    const float* X = (op == 0 ? q : (op == 1 ? k : v)) + (size_t)m0 * DIN;
    const float* W = (op == 0 ? Wq : (op == 1 ? Wk : Wv)) + (size_t)h * DIN * HDIM;
    float* C = (op == 0 ? g_Q : (op == 1 ? g_K : g_V))
               + (size_t)h * BN_TOT * HDIM + (size_t)m0 * HDIM;

    gemm_tile_128x64(X, DIN, W, HDIM, C, HDIM, Xs, Ws);
}

// ============================================================
// Mask pack: 64 int32 -> 1 uint64 bitmask per (bq, key-tile) via ballot.
// ============================================================
__global__ __launch_bounds__(256)
void pack_mask(const int* __restrict__ mask)
{
    int w = (blockIdx.x * 256 + threadIdx.x) >> 5;   // word index: bq*16 + kt
    int lane = threadIdx.x & 31;
    const int* src = mask + (size_t)w * 64;
    unsigned lo = __ballot_sync(0xffffffffu, src[lane] != 0);
    unsigned hi = __ballot_sync(0xffffffffu, src[lane + 32] != 0);
    if (lane == 0)
        g_Mb[w] = ((unsigned long long)hi << 32) | (unsigned long long)lo;
}

// ============================================================
// wmma tf32 GEMM (out projection). Measured good (R4/R5).
// ============================================================
#define BK    32
#define LDA_S 40
#define LDB_S 72

__global__ __launch_bounds__(256)
void gemm_wmma(const float* __restrict__ A,
               const float* __restrict__ B,
               float* __restrict__ C,
               size_t bblk_stride, int ldb,
               size_t cblk_stride, int ldc)
{
    __shared__ __align__(32) float sA[128 * LDA_S];
    __shared__ __align__(32) float sB[BK * LDB_S];

    const int tid = threadIdx.x;
    const int wid = tid >> 5;
    const int wm  = wid & 3;
    const int wn  = wid >> 2;

    const float* At = A + (size_t)blockIdx.x * 128 * DIN;
    const float* Bt = B + (size_t)blockIdx.y * bblk_stride;
    float*       Ct = C + (size_t)blockIdx.y * cblk_stride
                        + (size_t)blockIdx.x * 128 * ldc;

    wmma::fragment<wmma::accumulator, 16, 16, 8, float> acc[2][2];
#pragma unroll
    for (int i = 0; i < 2; i++)
#pragma unroll
        for (int j = 0; j < 2; j++) wmma::fill_fragment(acc[i][j], 0.0f);

    for (int c = 0; c < DIN / BK; ++c) {
        const int k0 = c * BK;
#pragma unroll
        for (int i = 0; i < 4; ++i) {
            int idx = tid + i * 256;
            int m  = idx >> 3;
            int c4 = idx & 7;
            float4 xv = *(const float4*)(At + (size_t)m * DIN + k0 + c4 * 4);
            xv.x = f2tf32_rna(xv.x); xv.y = f2tf32_rna(xv.y);
            xv.z = f2tf32_rna(xv.z); xv.w = f2tf32_rna(xv.w);
            *(float4*)(sA + m * LDA_S + c4 * 4) = xv;
        }
#pragma unroll
        for (int i = 0; i < 2; ++i) {
            int idx = tid + i * 256;
            int kk = idx >> 4;
            int c4 = idx & 15;
            float4 xv = *(const float4*)(Bt + (size_t)(k0 + kk) * ldb + c4 * 4);
            xv.x = f2tf32_rna(xv.x); xv.y = f2tf32_rna(xv.y);
            xv.z = f2tf32_rna(xv.z); xv.w = f2tf32_rna(xv.w);
            *(float4*)(sB + kk * LDB_S + c4 * 4) = xv;
        }
        __syncthreads();

#pragma unroll
        for (int ks = 0; ks < BK / 8; ++ks) {
            wmma::fragment<wmma::matrix_a, 16, 16, 8, wmma::precision::tf32, wmma::row_major> af[2];
            wmma::fragment<wmma::matrix_b, 16, 16, 8, wmma::precision::tf32, wmma::row_major> bf[2];
#pragma unroll
            for (int i = 0; i < 2; i++)
                wmma::load_matrix_sync(af[i], sA + (wm * 32 + i * 16) * LDA_S + ks * 8, LDA_S);
#pragma unroll
            for (int j = 0; j < 2; j++)
                wmma::load_matrix_sync(bf[j], sB + (ks * 8) * LDB_S + wn * 32 + j * 16, LDB_S);
#pragma unroll
            for (int i = 0; i < 2; i++)
#pragma unroll
                for (int j = 0; j < 2; j++)
                    wmma::mma_sync(acc[i][j], af[i], bf[j], acc[i][j]);
        }
        __syncthreads();
    }

#pragma unroll
    for (int i = 0; i < 2; i++)
#pragma unroll
        for (int j = 0; j < 2; j++)
            wmma::store_matrix_sync(
                Ct + (size_t)(wm * 32 + i * 16) * ldc + wn * 32 + j * 16,
                acc[i][j], ldc, wmma::mem_row_major);
}

// ============================================================
// FA2-style flash attention with raw mma.sync m16n8k8 tf32.
// Block: 256 threads / 8 warps; warp w owns q-rows [q0+16w, q0+16w+16).
// 16 key-tiles of 64. Q in persistent A-frags; O in persistent accumulators;
// softmax in registers (known C layout); P via per-warp smem strip.
// smem: sK[64][68] + sV[64][72] + sP[128][68] = 69 KB -> dynamic.
// ============================================================
#define LDK 68
#define LDV 72
#define LDP 68
#define ATTN_SMEM ((64 * LDK + 64 * LDV + 128 * LDP) * 4)

__global__ __launch_bounds__(256, 2)
void attn_mma()
{
    extern __shared__ float sm[];
    float* sK = sm;
    float* sV = sK + 64 * LDK;
    float* sP = sV + 64 * LDV;

    const int tid  = threadIdx.x;
    const int w    = tid >> 5;
    const int lane = tid & 31;
    const int g    = lane >> 2;
    const int t    = lane & 3;
    const int q0   = blockIdx.x * 128;
    const int b    = blockIdx.y;
    const int h    = blockIdx.z;

    const float* Qg = g_Q + ((size_t)(h * BATCH + b) * NQ + q0) * HDIM;
    const float* Kg = g_K + (size_t)(h * BATCH + b) * NK * HDIM;
    const float* Vg = g_V + (size_t)(h * BATCH + b) * NK * HDIM;

    // Persistent Q A-fragments (8 k-chunks x 4 regs), scaled + tf32-rounded
    uint32_t qf[8][4];
#pragma unroll
    for (int kc = 0; kc < 8; ++kc) {
        const float* r0 = Qg + (size_t)(w * 16 + g) * HDIM + kc * 8;
        const float* r1 = Qg + (size_t)(w * 16 + g + 8) * HDIM + kc * 8;
        qf[kc][0] = __float_as_uint(f2tf32_rna(r0[t] * NORM_F));
        qf[kc][1] = __float_as_uint(f2tf32_rna(r1[t] * NORM_F));
        qf[kc][2] = __float_as_uint(f2tf32_rna(r0[t + 4] * NORM_F));
        qf[kc][3] = __float_as_uint(f2tf32_rna(r1[t + 4] * NORM_F));
    }

    float oacc[8][4];
#pragma unroll
    for (int nt = 0; nt < 8; ++nt)
#pragma unroll
        for (int j = 0; j < 4; ++j) oacc[nt][j] = 0.f;
    float m0 = -1e30f, m1 = -1e30f;
    float l0 = 0.f, l1 = 0.f;

    const unsigned long long* mb_row0 = g_Mb + ((size_t)b * NQ + q0 + w * 16 + g) * (NK / 64);
    const unsigned long long* mb_row1 = mb_row0 + 8 * (NK / 64);
    float* sPw = sP + (w * 16) * LDP;   // per-warp strip

    for (int kt = 0; kt < NK / 64; ++kt) {
        __syncthreads();   // all warps done reading sK/sV from previous tile
        // Stage K (ld 68) and V (ld 72) tiles [64x64], tf32-rounded
#pragma unroll
        for (int i = 0; i < 4; ++i) {
            int idx = tid + i * 256;
            int r  = idx >> 4;
            int c4 = idx & 15;
            float4 kv = *(const float4*)(Kg + (size_t)(kt * 64 + r) * HDIM + c4 * 4);
            kv.x = f2tf32_rna(kv.x); kv.y = f2tf32_rna(kv.y);
            kv.z = f2tf32_rna(kv.z); kv.w = f2tf32_rna(kv.w);
            *(float4*)(sK + r * LDK + c4 * 4) = kv;
            float4 vv = *(const float4*)(Vg + (size_t)(kt * 64 + r) * HDIM + c4 * 4);
            vv.x = f2tf32_rna(vv.x); vv.y = f2tf32_rna(vv.y);
            vv.z = f2tf32_rna(vv.z); vv.w = f2tf32_rna(vv.w);
            *(float4*)(sV + r * LDV + c4 * 4) = vv;
        }
        __syncthreads();

        // ---- S = Q @ K^T : 8 n-tiles x 8 k-chunks ----
        float sacc[8][4];
#pragma unroll
        for (int nt = 0; nt < 8; ++nt) {
#pragma unroll
            for (int j = 0; j < 4; ++j) sacc[nt][j] = 0.f;
#pragma unroll
            for (int kc = 0; kc < 8; ++kc) {
                uint32_t bfr[2];
                const float* kb = sK + (nt * 8 + g) * LDK + kc * 8;
                bfr[0] = __float_as_uint(kb[t]);
                bfr[1] = __float_as_uint(kb[t + 4]);
                mma_tf32(sacc[nt], qf[kc], bfr);
            }
        }

        // ---- masked online softmax in registers ----
        unsigned long long mb0 = mb_row0[kt];
        unsigned long long mb1 = mb_row1[kt];
        float tmax0 = -1e30f, tmax1 = -1e30f;
#pragma unroll
        for (int nt = 0; nt < 8; ++nt) {
            int c0 = nt * 8 + 2 * t, c1 = c0 + 1;
            if ((mb0 >> c0) & 1ull) sacc[nt][0] = -1e30f;
            if ((mb0 >> c1) & 1ull) sacc[nt][1] = -1e30f;
            if ((mb1 >> c0) & 1ull) sacc[nt][2] = -1e30f;
            if ((mb1 >> c1) & 1ull) sacc[nt][3] = -1e30f;
            tmax0 = fmaxf(tmax0, fmaxf(sacc[nt][0], sacc[nt][1]));
            tmax1 = fmaxf(tmax1, fmaxf(sacc[nt][2], sacc[nt][3]));
        }
        tmax0 = fmaxf(tmax0, __shfl_xor_sync(0xffffffffu, tmax0, 1));
        tmax0 = fmaxf(tmax0, __shfl_xor_sync(0xffffffffu, tmax0, 2));
        tmax1 = fmaxf(tmax1, __shfl_xor_sync(0xffffffffu, tmax1, 1));
        tmax1 = fmaxf(tmax1, __shfl_xor_sync(0xffffffffu, tmax1, 2));

        float mn0 = fmaxf(m0, tmax0);
        float mn1 = fmaxf(m1, tmax1);
        float sc0 = __expf(m0 - mn0);
        float sc1 = __expf(m1 - mn1);
        m0 = mn0; m1 = mn1;

        float ps0 = 0.f, ps1 = 0.f;
#pragma unroll
        for (int nt = 0; nt < 8; ++nt) {
            float p0 = __expf(sacc[nt][0] - mn0);
            float p1 = __expf(sacc[nt][1] - mn0);
            float p2 = __expf(sacc[nt][2] - mn1);
            float p3 = __expf(sacc[nt][3] - mn1);
            ps0 += p0 + p1;
            ps1 += p2 + p3;
            float2 lo = make_float2(f2tf32_rna(p0), f2tf32_rna(p1));
            float2 hi = make_float2(f2tf32_rna(p2), f2tf32_rna(p3));
            *(float2*)(sPw + g * LDP + nt * 8 + 2 * t) = lo;
            *(float2*)(sPw + (g + 8) * LDP + nt * 8 + 2 * t) = hi;
        }
        ps0 += __shfl_xor_sync(0xffffffffu, ps0, 1);
        ps0 += __shfl_xor_sync(0xffffffffu, ps0, 2);
        ps1 += __shfl_xor_sync(0xffffffffu, ps1, 1);
        ps1 += __shfl_xor_sync(0xffffffffu, ps1, 2);
        l0 = l0 * sc0 + ps0;
        l1 = l1 * sc1 + ps1;

        // rescale O (c0,c1 <- row g; c2,c3 <- row g+8)
#pragma unroll
        for (int nt = 0; nt < 8; ++nt) {
            oacc[nt][0] *= sc0; oacc[nt][1] *= sc0;
            oacc[nt][2] *= sc1; oacc[nt][3] *= sc1;
        }
        __syncwarp();   // P strip visible within warp

        // ---- O += P @ V ----
#pragma unroll
        for (int kc = 0; kc < 8; ++kc) {
            uint32_t pa[4];
            const float* p0r = sPw + g * LDP + kc * 8;
            const float* p1r = sPw + (g + 8) * LDP + kc * 8;
            pa[0] = __float_as_uint(p0r[t]);
            pa[1] = __float_as_uint(p1r[t]);
            pa[2] = __float_as_uint(p0r[t + 4]);
            pa[3] = __float_as_uint(p1r[t + 4]);
#pragma unroll
            for (int nt = 0; nt < 8; ++nt) {
                uint32_t bfr[2];
                bfr[0] = __float_as_uint(sV[(kc * 8 + t) * LDV + nt * 8 + g]);
                bfr[1] = __float_as_uint(sV[(kc * 8 + t + 4) * LDV + nt * 8 + g]);
                mma_tf32(oacc[nt], pa, bfr);
            }
        }
        __syncwarp();   // done reading sPw before next-iter overwrite
    }

    // Normalize and write heads: g_H[bn][h*64+v]
    float inv0 = (l0 > 0.f) ? (1.f / l0) : 0.f;
    float inv1 = (l1 > 0.f) ? (1.f / l1) : 0.f;
    float* o0 = g_H + ((size_t)(b * NQ + q0 + w * 16 + g)) * DIN + h * HDIM;
    float* o1 = g_H + ((size_t)(b * NQ + q0 + w * 16 + g + 8)) * DIN + h * HDIM;
#pragma unroll
    for (int nt = 0; nt < 8; ++nt) {
        *(float2*)(o0 + nt * 8 + 2 * t) = make_float2(oacc[nt][0] * inv0, oacc[nt][1] * inv0);
        *(float2*)(o1 + nt * 8 + 2 * t) = make_float2(oacc[nt][2] * inv1, oacc[nt][3] * inv1);
    }
}

// ============================================================
extern "C" void kernel_launch(void* const* d_in, const int* in_sizes, int n_in,
                              void* d_out, int out_size)
{
    const float* q  = (const float*)d_in[0];
    const float* k  = (const float*)d_in[1];
    const float* v  = (const float*)d_in[2];
    const int*   mask = (const int*)d_in[3];
    const float* Wq = (const float*)d_in[4];
    const float* Wk = (const float*)d_in[5];
    const float* Wv = (const float*)d_in[6];
    const float* Wo = (const float*)d_in[7];
    float* out = (float*)d_out;

    float *pH;
    cudaGetSymbolAddress((void**)&pH, g_H);

    static bool attr_set = false;
    if (!attr_set) {
        cudaFuncSetAttribute(attn_mma,
                             cudaFuncAttributeMaxDynamicSharedMemorySize,
                             ATTN_SMEM);
        attr_set = true;
    }

    // QKV projections: exact fp32 SIMT (protects the softmax error budget)
    qkv_proj<<<dim3(BN_TOT / 128, NHEADS, 3), 256>>>(q, k, v, Wq, Wk, Wv);

    // Pack mask to bitmasks: 16384*16 words, one warp per word
    pack_mask<<<(BN_TOT * (NK / 64)) / 8, 256>>>(mask);

    // Flash attention (raw mma.sync tf32, register softmax)
    attn_mma<<<dim3(NQ / 128, BATCH, NHEADS), 256, ATTN_SMEM>>>();

    // Output projection: wmma tf32; Wo is [512(k), 512(e)] row-major
    gemm_wmma<<<dim3(BN_TOT / 128, DIN / HDIM), 256>>>(
        pH, Wo, out, (size_t)HDIM, DIN, (size_t)HDIM, DIN);
}

// round 7
// speedup vs baseline: 1.9337x; 1.0052x over previous
#include <cuda_runtime.h>
#include <cuda_bf16.h>
#include <mma.h>
#include <cstdint>

using namespace nvcuda;

// Problem constants
#define BATCH   16
#define NQ      1024
#define NK      1024
#define DIN     512
#define NHEADS  8
#define HDIM    64
#define BN_TOT  (BATCH * NQ)       // 16384
#define NORM_F  0.125f             // 1/sqrt(64)

// -------- scratch (device globals: allocation-free) --------
__device__ float g_Q[(size_t)NHEADS * BN_TOT * HDIM];   // [h][bn][64]
__device__ float g_K[(size_t)NHEADS * BN_TOT * HDIM];
__device__ float g_V[(size_t)NHEADS * BN_TOT * HDIM];
__device__ float g_H[(size_t)BN_TOT * DIN];             // [bn][h*64+v]
__device__ unsigned long long g_Mb[(size_t)BN_TOT * (NK / 64)];  // packed mask bits

__device__ __forceinline__ float f2tf32_rna(float x) {
    uint32_t r;
    asm("cvt.rna.tf32.f32 %0, %1;" : "=r"(r) : "f"(x));
    return __uint_as_float(r);
}

// m16n8k8 tf32 mma (g=lane>>2, t=lane&3):
//   A: a0(g,t) a1(g+8,t) a2(g,t+4) a3(g+8,t+4)
//   B: b0(k=t,n=g) b1(k=t+4,n=g)
//   C: c0(g,2t) c1(g,2t+1) c2(g+8,2t) c3(g+8,2t+1)
__device__ __forceinline__ void mma_tf32(float* c, const uint32_t* a, const uint32_t* b) {
    asm volatile(
        "mma.sync.aligned.m16n8k8.row.col.f32.tf32.tf32.f32 "
        "{%0,%1,%2,%3}, {%4,%5,%6,%7}, {%8,%9}, {%0,%1,%2,%3};"
        : "+f"(c[0]), "+f"(c[1]), "+f"(c[2]), "+f"(c[3])
        : "r"(a[0]), "r"(a[1]), "r"(a[2]), "r"(a[3]), "r"(b[0]), "r"(b[1]));
}

// ============================================================
// Fused QKV projection, exact fp32 SIMT, roofline-oriented:
// one [16384,512] @ [512,512] GEMM per op (8 heads fused as column blocks).
// 128x128 tile, 256 threads, 8x8 microtile, BK=16, double-buffered smem,
// ONE __syncthreads per k-chunk. Epilogue scatters to g_{Q,K,V}[h][bn][64].
// grid = (128 m-tiles, 4 n-tiles, 3 ops)
// ============================================================
#define QBM 128
#define QBN 128
#define QBK 16

__global__ __launch_bounds__(256, 2)
void qkv_proj2(const float* __restrict__ q,
               const float* __restrict__ k,
               const float* __restrict__ v,
               const float* __restrict__ Wq,
               const float* __restrict__ Wk,
               const float* __restrict__ Wv)
{
    __shared__ float Xs[2][QBK][QBM];   // transposed A chunk (k-major)
    __shared__ float Ws[2][QBK][QBN];   // B chunk (row-major)

    const int tid = threadIdx.x;
    const int tx  = tid & 15;    // n dir: 16 x 8 cols
    const int ty  = tid >> 4;    // m dir: 16 x 8 rows
    const int op  = blockIdx.z;
    const int m0  = blockIdx.x * QBM;
    const int n0  = blockIdx.y * QBN;

    const float* X = (op == 0 ? q : (op == 1 ? k : v));
    const float* W = (op == 0 ? Wq : (op == 1 ? Wk : Wv));
    float* Cb      = (op == 0 ? g_Q : (op == 1 ? g_K : g_V));

    // --- staging address patterns (lane-constant) ---
    // A: 512 float4 per chunk; element idx = tid + i*256 (i<2):
    //    mA = idx&127 (consecutive lanes -> consecutive m: conflict-free STS),
    //    k4 = idx>>7 in {0,1} then {2,3}.
    const int mA  = tid & 127;
    const int k4a = tid >> 7;                 // 0 or 1; +2 on second iter
    const float* Ag = X + (size_t)(m0 + mA) * DIN;
    // B: 512 float4 per chunk; idx = tid + i*256:
    //    kk = idx>>5 (0..7 then 8..15), c4 = tid&31 -> global col c4*4.
    //    W head-major: col c -> h=(c>>6), offset h*512*64 + k*64 + (c&63).
    const int kkB = tid >> 5;                 // 0..7; +8 on second iter
    const int c4  = tid & 31;
    const float* Bg = W + (size_t)((n0 + c4 * 4) >> 6) * (DIN * HDIM)
                        + ((n0 + c4 * 4) & 63);

    float acc[8][8];
#pragma unroll
    for (int i = 0; i < 8; i++)
#pragma unroll
        for (int j = 0; j < 8; j++) acc[i][j] = 0.f;

    float4 ar[2], br[2];
    // prologue: load + store chunk 0 into buf 0
#pragma unroll
    for (int i = 0; i < 2; ++i) {
        ar[i] = *(const float4*)(Ag + (k4a + 2 * i) * 4);
        br[i] = *(const float4*)(Bg + (size_t)(kkB + 8 * i) * HDIM);
    }
#pragma unroll
    for (int i = 0; i < 2; ++i) {
        int kr = (k4a + 2 * i) * 4;
        Xs[0][kr + 0][mA] = ar[i].x;
        Xs[0][kr + 1][mA] = ar[i].y;
        Xs[0][kr + 2][mA] = ar[i].z;
        Xs[0][kr + 3][mA] = ar[i].w;
        *(float4*)(&Ws[0][kkB + 8 * i][c4 * 4]) = br[i];
    }
    __syncthreads();

    for (int c = 0; c < DIN / QBK; ++c) {
        const int cur = c & 1;
        if (c < DIN / QBK - 1) {
            const int k0n = (c + 1) * QBK;
#pragma unroll
            for (int i = 0; i < 2; ++i) {
                ar[i] = *(const float4*)(Ag + k0n + (k4a + 2 * i) * 4);
                br[i] = *(const float4*)(Bg + (size_t)(k0n + kkB + 8 * i) * HDIM);
            }
        }

#pragma unroll
        for (int kk = 0; kk < QBK; ++kk) {
            float a[8], b[8];
            *(float4*)(a)     = *(const float4*)(&Xs[cur][kk][ty * 8]);
            *(float4*)(a + 4) = *(const float4*)(&Xs[cur][kk][ty * 8 + 4]);
            *(float4*)(b)     = *(const float4*)(&Ws[cur][kk][tx * 8]);
            *(float4*)(b + 4) = *(const float4*)(&Ws[cur][kk][tx * 8 + 4]);
#pragma unroll
            for (int i = 0; i < 8; i++)
#pragma unroll
                for (int j = 0; j < 8; j++)
                    acc[i][j] = fmaf(a[i], b[j], acc[i][j]);
        }

        if (c < DIN / QBK - 1) {
            const int nxt = cur ^ 1;
#pragma unroll
            for (int i = 0; i < 2; ++i) {
                int kr = (k4a + 2 * i) * 4;
                Xs[nxt][kr + 0][mA] = ar[i].x;
                Xs[nxt][kr + 1][mA] = ar[i].y;
                Xs[nxt][kr + 2][mA] = ar[i].z;
                Xs[nxt][kr + 3][mA] = ar[i].w;
                *(float4*)(&Ws[nxt][kkB + 8 * i][c4 * 4]) = br[i];
            }
            __syncthreads();
        }
    }

    // Epilogue: scatter to per-head layout Cb[h][bn][64].
    const int cgl = n0 + tx * 8;          // global col (8 cols, same head)
    const int h   = cgl >> 6;
    const int nh  = cgl & 63;
    float* Crow = Cb + (size_t)h * BN_TOT * HDIM
                     + (size_t)(m0 + ty * 8) * HDIM + nh;
#pragma unroll
    for (int i = 0; i < 8; i++) {
        *(float4*)(Crow + (size_t)i * HDIM)     =
            make_float4(acc[i][0], acc[i][1], acc[i][2], acc[i][3]);
        *(float4*)(Crow + (size_t)i * HDIM + 4) =
            make_float4(acc[i][4], acc[i][5], acc[i][6], acc[i][7]);
    }
}

// ============================================================
// Mask pack: 64 int32 -> 1 uint64 bitmask per (bq, key-tile) via ballot.
// ============================================================
__global__ __launch_bounds__(256)
void pack_mask(const int* __restrict__ mask)
{
    int w = (blockIdx.x * 256 + threadIdx.x) >> 5;
    int lane = threadIdx.x & 31;
    const int* src = mask + (size_t)w * 64;
    unsigned lo = __ballot_sync(0xffffffffu, src[lane] != 0);
    unsigned hi = __ballot_sync(0xffffffffu, src[lane + 32] != 0);
    if (lane == 0)
        g_Mb[w] = ((unsigned long long)hi << 32) | (unsigned long long)lo;
}

// ============================================================
// wmma tf32 GEMM (out projection). Measured good (R4/R6).
// ============================================================
#define BK    32
#define LDA_S 40
#define LDB_S 72

__global__ __launch_bounds__(256)
void gemm_wmma(const float* __restrict__ A,
               const float* __restrict__ B,
               float* __restrict__ C,
               size_t bblk_stride, int ldb,
               size_t cblk_stride, int ldc)
{
    __shared__ __align__(32) float sA[128 * LDA_S];
    __shared__ __align__(32) float sB[BK * LDB_S];

    const int tid = threadIdx.x;
    const int wid = tid >> 5;
    const int wm  = wid & 3;
    const int wn  = wid >> 2;

    const float* At = A + (size_t)blockIdx.x * 128 * DIN;
    const float* Bt = B + (size_t)blockIdx.y * bblk_stride;
    float*       Ct = C + (size_t)blockIdx.y * cblk_stride
                        + (size_t)blockIdx.x * 128 * ldc;

    wmma::fragment<wmma::accumulator, 16, 16, 8, float> acc[2][2];
#pragma unroll
    for (int i = 0; i < 2; i++)
#pragma unroll
        for (int j = 0; j < 2; j++) wmma::fill_fragment(acc[i][j], 0.0f);

    for (int c = 0; c < DIN / BK; ++c) {
        const int k0 = c * BK;
#pragma unroll
        for (int i = 0; i < 4; ++i) {
            int idx = tid + i * 256;
            int m  = idx >> 3;
            int c4 = idx & 7;
            float4 xv = *(const float4*)(At + (size_t)m * DIN + k0 + c4 * 4);
            xv.x = f2tf32_rna(xv.x); xv.y = f2tf32_rna(xv.y);
            xv.z = f2tf32_rna(xv.z); xv.w = f2tf32_rna(xv.w);
            *(float4*)(sA + m * LDA_S + c4 * 4) = xv;
        }
#pragma unroll
        for (int i = 0; i < 2; ++i) {
            int idx = tid + i * 256;
            int kk = idx >> 4;
            int c4 = idx & 15;
            float4 xv = *(const float4*)(Bt + (size_t)(k0 + kk) * ldb + c4 * 4);
            xv.x = f2tf32_rna(xv.x); xv.y = f2tf32_rna(xv.y);
            xv.z = f2tf32_rna(xv.z); xv.w = f2tf32_rna(xv.w);
            *(float4*)(sB + kk * LDB_S + c4 * 4) = xv;
        }
        __syncthreads();

#pragma unroll
        for (int ks = 0; ks < BK / 8; ++ks) {
            wmma::fragment<wmma::matrix_a, 16, 16, 8, wmma::precision::tf32, wmma::row_major> af[2];
            wmma::fragment<wmma::matrix_b, 16, 16, 8, wmma::precision::tf32, wmma::row_major> bf[2];
#pragma unroll
            for (int i = 0; i < 2; i++)
                wmma::load_matrix_sync(af[i], sA + (wm * 32 + i * 16) * LDA_S + ks * 8, LDA_S);
#pragma unroll
            for (int j = 0; j < 2; j++)
                wmma::load_matrix_sync(bf[j], sB + (ks * 8) * LDB_S + wn * 32 + j * 16, LDB_S);
#pragma unroll
            for (int i = 0; i < 2; i++)
#pragma unroll
                for (int j = 0; j < 2; j++)
                    wmma::mma_sync(acc[i][j], af[i], bf[j], acc[i][j]);
        }
        __syncthreads();
    }

#pragma unroll
    for (int i = 0; i < 2; i++)
#pragma unroll
        for (int j = 0; j < 2; j++)
            wmma::store_matrix_sync(
                Ct + (size_t)(wm * 32 + i * 16) * ldc + wn * 32 + j * 16,
                acc[i][j], ldc, wmma::mem_row_major);
}

// ============================================================
// FA2-style flash attention with raw mma.sync m16n8k8 tf32. (R6, measured good)
// ============================================================
#define LDK 68
#define LDV 72
#define LDP 68
#define ATTN_SMEM ((64 * LDK + 64 * LDV + 128 * LDP) * 4)

__global__ __launch_bounds__(256, 2)
void attn_mma()
{
    extern __shared__ float sm[];
    float* sK = sm;
    float* sV = sK + 64 * LDK;
    float* sP = sV + 64 * LDV;

    const int tid  = threadIdx.x;
    const int w    = tid >> 5;
    const int lane = tid & 31;
    const int g    = lane >> 2;
    const int t    = lane & 3;
    const int q0   = blockIdx.x * 128;
    const int b    = blockIdx.y;
    const int h    = blockIdx.z;

    const float* Qg = g_Q + ((size_t)(h * BATCH + b) * NQ + q0) * HDIM;
    const float* Kg = g_K + (size_t)(h * BATCH + b) * NK * HDIM;
    const float* Vg = g_V + (size_t)(h * BATCH + b) * NK * HDIM;

    uint32_t qf[8][4];
#pragma unroll
    for (int kc = 0; kc < 8; ++kc) {
        const float* r0 = Qg + (size_t)(w * 16 + g) * HDIM + kc * 8;
        const float* r1 = Qg + (size_t)(w * 16 + g + 8) * HDIM + kc * 8;
        qf[kc][0] = __float_as_uint(f2tf32_rna(r0[t] * NORM_F));
        qf[kc][1] = __float_as_uint(f2tf32_rna(r1[t] * NORM_F));
        qf[kc][2] = __float_as_uint(f2tf32_rna(r0[t + 4] * NORM_F));
        qf[kc][3] = __float_as_uint(f2tf32_rna(r1[t + 4] * NORM_F));
    }

    float oacc[8][4];
#pragma unroll
    for (int nt = 0; nt < 8; ++nt)
#pragma unroll
        for (int j = 0; j < 4; ++j) oacc[nt][j] = 0.f;
    float m0 = -1e30f, m1 = -1e30f;
    float l0 = 0.f, l1 = 0.f;

    const unsigned long long* mb_row0 = g_Mb + ((size_t)b * NQ + q0 + w * 16 + g) * (NK / 64);
    const unsigned long long* mb_row1 = mb_row0 + 8 * (NK / 64);
    float* sPw = sP + (w * 16) * LDP;

    for (int kt = 0; kt < NK / 64; ++kt) {
        __syncthreads();
#pragma unroll
        for (int i = 0; i < 4; ++i) {
            int idx = tid + i * 256;
            int r  = idx >> 4;
            int c4 = idx & 15;
            float4 kv = *(const float4*)(Kg + (size_t)(kt * 64 + r) * HDIM + c4 * 4);
            kv.x = f2tf32_rna(kv.x); kv.y = f2tf32_rna(kv.y);
            kv.z = f2tf32_rna(kv.z); kv.w = f2tf32_rna(kv.w);
            *(float4*)(sK + r * LDK + c4 * 4) = kv;
            float4 vv = *(const float4*)(Vg + (size_t)(kt * 64 + r) * HDIM + c4 * 4);
            vv.x = f2tf32_rna(vv.x); vv.y = f2tf32_rna(vv.y);
            vv.z = f2tf32_rna(vv.z); vv.w = f2tf32_rna(vv.w);
            *(float4*)(sV + r * LDV + c4 * 4) = vv;
        }
        __syncthreads();

        float sacc[8][4];
#pragma unroll
        for (int nt = 0; nt < 8; ++nt) {
#pragma unroll
            for (int j = 0; j < 4; ++j) sacc[nt][j] = 0.f;
#pragma unroll
            for (int kc = 0; kc < 8; ++kc) {
                uint32_t bfr[2];
                const float* kb = sK + (nt * 8 + g) * LDK + kc * 8;
                bfr[0] = __float_as_uint(kb[t]);
                bfr[1] = __float_as_uint(kb[t + 4]);
                mma_tf32(sacc[nt], qf[kc], bfr);
            }
        }

        unsigned long long mb0 = mb_row0[kt];
        unsigned long long mb1 = mb_row1[kt];
        float tmax0 = -1e30f, tmax1 = -1e30f;
#pragma unroll
        for (int nt = 0; nt < 8; ++nt) {
            int c0 = nt * 8 + 2 * t, c1 = c0 + 1;
            if ((mb0 >> c0) & 1ull) sacc[nt][0] = -1e30f;
            if ((mb0 >> c1) & 1ull) sacc[nt][1] = -1e30f;
            if ((mb1 >> c0) & 1ull) sacc[nt][2] = -1e30f;
            if ((mb1 >> c1) & 1ull) sacc[nt][3] = -1e30f;
            tmax0 = fmaxf(tmax0, fmaxf(sacc[nt][0], sacc[nt][1]));
            tmax1 = fmaxf(tmax1, fmaxf(sacc[nt][2], sacc[nt][3]));
        }
        tmax0 = fmaxf(tmax0, __shfl_xor_sync(0xffffffffu, tmax0, 1));
        tmax0 = fmaxf(tmax0, __shfl_xor_sync(0xffffffffu, tmax0, 2));
        tmax1 = fmaxf(tmax1, __shfl_xor_sync(0xffffffffu, tmax1, 1));
        tmax1 = fmaxf(tmax1, __shfl_xor_sync(0xffffffffu, tmax1, 2));

        float mn0 = fmaxf(m0, tmax0);
        float mn1 = fmaxf(m1, tmax1);
        float sc0 = __expf(m0 - mn0);
        float sc1 = __expf(m1 - mn1);
        m0 = mn0; m1 = mn1;

        float ps0 = 0.f, ps1 = 0.f;
#pragma unroll
        for (int nt = 0; nt < 8; ++nt) {
            float p0 = __expf(sacc[nt][0] - mn0);
            float p1 = __expf(sacc[nt][1] - mn0);
            float p2 = __expf(sacc[nt][2] - mn1);
            float p3 = __expf(sacc[nt][3] - mn1);
            ps0 += p0 + p1;
            ps1 += p2 + p3;
            float2 lo = make_float2(f2tf32_rna(p0), f2tf32_rna(p1));
            float2 hi = make_float2(f2tf32_rna(p2), f2tf32_rna(p3));
            *(float2*)(sPw + g * LDP + nt * 8 + 2 * t) = lo;
            *(float2*)(sPw + (g + 8) * LDP + nt * 8 + 2 * t) = hi;
        }
        ps0 += __shfl_xor_sync(0xffffffffu, ps0, 1);
        ps0 += __shfl_xor_sync(0xffffffffu, ps0, 2);
        ps1 += __shfl_xor_sync(0xffffffffu, ps1, 1);
        ps1 += __shfl_xor_sync(0xffffffffu, ps1, 2);
        l0 = l0 * sc0 + ps0;
        l1 = l1 * sc1 + ps1;

#pragma unroll
        for (int nt = 0; nt < 8; ++nt) {
            oacc[nt][0] *= sc0; oacc[nt][1] *= sc0;
            oacc[nt][2] *= sc1; oacc[nt][3] *= sc1;
        }
        __syncwarp();

#pragma unroll
        for (int kc = 0; kc < 8; ++kc) {
            uint32_t pa[4];
            const float* p0r = sPw + g * LDP + kc * 8;
            const float* p1r = sPw + (g + 8) * LDP + kc * 8;
            pa[0] = __float_as_uint(p0r[t]);
            pa[1] = __float_as_uint(p1r[t]);
            pa[2] = __float_as_uint(p0r[t + 4]);
            pa[3] = __float_as_uint(p1r[t + 4]);
#pragma unroll
            for (int nt = 0; nt < 8; ++nt) {
                uint32_t bfr[2];
                bfr[0] = __float_as_uint(sV[(kc * 8 + t) * LDV + nt * 8 + g]);
                bfr[1] = __float_as_uint(sV[(kc * 8 + t + 4) * LDV + nt * 8 + g]);
                mma_tf32(oacc[nt], pa, bfr);
            }
        }
        __syncwarp();
    }

    float inv0 = (l0 > 0.f) ? (1.f / l0) : 0.f;
    float inv1 = (l1 > 0.f) ? (1.f / l1) : 0.f;
    float* o0 = g_H + ((size_t)(b * NQ + q0 + w * 16 + g)) * DIN + h * HDIM;
    float* o1 = g_H + ((size_t)(b * NQ + q0 + w * 16 + g + 8)) * DIN + h * HDIM;
#pragma unroll
    for (int nt = 0; nt < 8; ++nt) {
        *(float2*)(o0 + nt * 8 + 2 * t) = make_float2(oacc[nt][0] * inv0, oacc[nt][1] * inv0);
        *(float2*)(o1 + nt * 8 + 2 * t) = make_float2(oacc[nt][2] * inv1, oacc[nt][3] * inv1);
    }
}

// ============================================================
extern "C" void kernel_launch(void* const* d_in, const int* in_sizes, int n_in,
                              void* d_out, int out_size)
{
    const float* q  = (const float*)d_in[0];
    const float* k  = (const float*)d_in[1];
    const float* v  = (const float*)d_in[2];
    const int*   mask = (const int*)d_in[3];
    const float* Wq = (const float*)d_in[4];
    const float* Wk = (const float*)d_in[5];
    const float* Wv = (const float*)d_in[6];
    const float* Wo = (const float*)d_in[7];
    float* out = (float*)d_out;

    float *pH;
    cudaGetSymbolAddress((void**)&pH, g_H);

    static bool attr_set = false;
    if (!attr_set) {
        cudaFuncSetAttribute(attn_mma,
                             cudaFuncAttributeMaxDynamicSharedMemorySize,
                             ATTN_SMEM);
        attr_set = true;
    }

    // QKV projections: exact fp32 SIMT, heads fused, double-buffered
    qkv_proj2<<<dim3(BN_TOT / QBM, DIN / QBN, 3), 256>>>(q, k, v, Wq, Wk, Wv);

    // Pack mask to bitmasks
    pack_mask<<<(BN_TOT * (NK / 64)) / 8, 256>>>(mask);

    // Flash attention (raw mma.sync tf32, register softmax)
    attn_mma<<<dim3(NQ / 128, BATCH, NHEADS), 256, ATTN_SMEM>>>();

    // Output projection: wmma tf32; Wo is [512(k), 512(e)] row-major
    gemm_wmma<<<dim3(BN_TOT / 128, DIN / HDIM), 256>>>(
        pH, Wo, out, (size_t)HDIM, DIN, (size_t)HDIM, DIN);
}